// round 9
// baseline (speedup 1.0000x reference)
#include <cuda_runtime.h>
#include <cuda_fp16.h>

// Problem constants
#define NW 16384   // words
#define WL 16      // word length
#define D  300     // hidden dim
#define DP 320     // padded channel count (zeros in [300,320))
#define NL 128     // letters
#define KS 3       // conv taps

// Encode config: slices 0/1 = 128 ch (2 words/warp), slice 2 = 64 ch
// (4 words/warp). 768 threads/CTA, 2 CTA/SM -> 48 warps/SM.
#define WPB 24
#define ENC_THREADS 768
#define B0 118
#define B1 118
#define B2 60
#define ENC_BLOCKS (B0 + B1 + B2)           // 296 = 2 CTA/SM * 148 SMs
#define ENC_SMEM (KS * NL * 128 * 2)        // 96 KB

// Fused prep kernel smem: ws[3][3][304] floats + es[128][153] floats
#define PREP_WS_FLOATS (3 * KS * 304)                    // 2736
#define PREP_ES_STRIDE 153
#define PREP_ES_FLOATS (NL * PREP_ES_STRIDE)             // 19584
#define PREP_SMEM ((PREP_WS_FLOATS + PREP_ES_FLOATS) * 4)  // 89280 B
#define PACK_BLOCKS 43                                    // 43*384 >= 16384

// Device scratch
__device__ __half g_Ph[KS][NL][DP];  // per-letter conv partials (fp16, padded)
                                     // k=1 tap has conv bias folded in
__device__ uint4  g_wpk[NW];         // packed letters: 16 u8 per word

// ---------------------------------------------------------------------------
// Kernel 1 (fused prep): blocks [0,43) pack each word's 16 letters into one
// uint4 of u8. Blocks [43,150) build P: block handles 3 output channels x
// 128 letters; emb is staged per-block in smem in 2 column tiles (152+148),
// padded stride 153 (conflict-free: gcd(153,32)=1). Bias folded into k=1 tap.
// ---------------------------------------------------------------------------
__global__ __launch_bounds__(384) void prep_kernel(const int* __restrict__ words,
                                                   const float* __restrict__ emb,
                                                   const float* __restrict__ w,
                                                   const float* __restrict__ bias) {
    if (blockIdx.x < PACK_BLOCKS) {
        const int n = blockIdx.x * 384 + threadIdx.x;
        if (n >= NW) return;
        unsigned r0 = 0, r1 = 0, r2 = 0, r3 = 0;
#pragma unroll
        for (int l = 0; l < 4; ++l)  r0 |= ((unsigned)words[l * NW + n] & 0xFF) << (l * 8);
#pragma unroll
        for (int l = 4; l < 8; ++l)  r1 |= ((unsigned)words[l * NW + n] & 0xFF) << ((l - 4) * 8);
#pragma unroll
        for (int l = 8; l < 12; ++l) r2 |= ((unsigned)words[l * NW + n] & 0xFF) << ((l - 8) * 8);
#pragma unroll
        for (int l = 12; l < 16; ++l) r3 |= ((unsigned)words[l * NW + n] & 0xFF) << ((l - 12) * 8);
        g_wpk[n] = make_uint4(r0, r1, r2, r3);
        return;
    }

    // ---- compute_P branch ----
    extern __shared__ float sm[];
    float* ws = sm;                          // [3][KS][304] de-interleaved w rows
    float* es = sm + PREP_WS_FLOATS;         // [128][153] emb column tile

    const int bp = blockIdx.x - PACK_BLOCKS;   // 0..106
    const int j  = threadIdx.x >> 7;           // 0..2
    const int v  = threadIdx.x & 127;
    const int ob = bp * 3;
    const int o  = ob + j;

    for (int t = threadIdx.x; t < 3 * D * KS; t += 384) {
        int jj = t / (D * KS), r = t % (D * KS);
        int oo = ob + jj;
        ws[(jj * KS + r % 3) * 304 + r / 3] = (oo < D) ? w[oo * D * KS + r] : 0.f;
    }

    float a0 = 0.f, a1 = 0.f, a2 = 0.f;
    const int tlen[2] = {152, 148};
    int i0 = 0;
#pragma unroll
    for (int t = 0; t < 2; ++t) {
        const int L = tlen[t];
        __syncthreads();
        // stage emb[:, i0:i0+L] as es[v][0:L] (float2 granularity)
        for (int idx = threadIdx.x; idx < NL * (L / 2); idx += 384) {
            int vv = idx / (L / 2), c = idx % (L / 2);
            float2 val = *(const float2*)(emb + vv * D + i0 + c * 2);
            es[vv * PREP_ES_STRIDE + c * 2]     = val.x;
            es[vv * PREP_ES_STRIDE + c * 2 + 1] = val.y;
        }
        __syncthreads();
        if (o < D) {
            const float* ev = es + v * PREP_ES_STRIDE;
            const float* w0p = ws + (j * KS + 0) * 304 + i0;
            const float* w1p = ws + (j * KS + 1) * 304 + i0;
            const float* w2p = ws + (j * KS + 2) * 304 + i0;
#pragma unroll 4
            for (int i = 0; i < L; i += 4) {
                float4 w0 = *(const float4*)(w0p + i);
                float4 w1 = *(const float4*)(w1p + i);
                float4 w2 = *(const float4*)(w2p + i);
                float e0 = ev[i], e1 = ev[i + 1], e2 = ev[i + 2], e3 = ev[i + 3];
                a0 = fmaf(e0, w0.x, a0); a1 = fmaf(e0, w1.x, a1); a2 = fmaf(e0, w2.x, a2);
                a0 = fmaf(e1, w0.y, a0); a1 = fmaf(e1, w1.y, a1); a2 = fmaf(e1, w2.y, a2);
                a0 = fmaf(e2, w0.z, a0); a1 = fmaf(e2, w1.z, a1); a2 = fmaf(e2, w2.z, a2);
                a0 = fmaf(e3, w0.w, a0); a1 = fmaf(e3, w1.w, a1); a2 = fmaf(e3, w2.w, a2);
            }
        }
        i0 += L;
    }

    if (o < DP) {
        bool real = (o < D);
        float bv = real ? bias[o] : 0.f;
        g_Ph[0][v][o] = __float2half(real ? a0 : 0.f);
        g_Ph[1][v][o] = __float2half(real ? (a1 + bv) : 0.f);  // bias folded into k=1
        g_Ph[2][v][o] = __float2half(real ? a2 : 0.f);
    }
}

// ---------------------------------------------------------------------------
// Kernel 2: encode. 296 blocks (118/118/60), 768 thr, 2 CTA/SM, 48 warps/SM.
// Slices 0/1 (128 ch): 2 words/warp. Slice 2 (64 ch): 4 words/warp. Letters
// via one broadcast LDG.128, prefetched. Per position: 3 conflict-free
// LDS.128 + half2 adds + half2 running max. Bias already in the table; the
// epilogue is just relu + fp32 store.
// ---------------------------------------------------------------------------
#define GETL(l) ((lw[(l) >> 2] >> (((l) & 3) * 8)) & 0xFF)

#define INNER_BODY(loidx)                                                        \
    half2 m0 = NEGI, m1 = NEGI, m2 = NEGI, m3 = NEGI;                            \
    _Pragma("unroll")                                                            \
    for (int l = 0; l < WL; ++l) {                                               \
        uint4 a = Pv[(NL + GETL(l)) * 16 + (loidx)];                             \
        half2 h0 = *(half2*)&a.x, h1 = *(half2*)&a.y;                            \
        half2 h2 = *(half2*)&a.z, h3 = *(half2*)&a.w;                            \
        if (l > 0) {                                                             \
            uint4 q = Pv[GETL(l - 1) * 16 + (loidx)];                            \
            h0 = __hadd2(h0, *(half2*)&q.x); h1 = __hadd2(h1, *(half2*)&q.y);    \
            h2 = __hadd2(h2, *(half2*)&q.z); h3 = __hadd2(h3, *(half2*)&q.w);    \
        }                                                                        \
        if (l < WL - 1) {                                                        \
            uint4 q = Pv[(2 * NL + GETL(l + 1)) * 16 + (loidx)];                 \
            h0 = __hadd2(h0, *(half2*)&q.x); h1 = __hadd2(h1, *(half2*)&q.y);    \
            h2 = __hadd2(h2, *(half2*)&q.z); h3 = __hadd2(h3, *(half2*)&q.w);    \
        }                                                                        \
        m0 = __hmax2(m0, h0); m1 = __hmax2(m1, h1);                              \
        m2 = __hmax2(m2, h2); m3 = __hmax2(m3, h3);                              \
    }

__global__ __launch_bounds__(ENC_THREADS, 2) void encode_kernel(float* __restrict__ out) {
    extern __shared__ uint4 Pv[];  // [KS*NL rows][16 uint4]

    int b = blockIdx.x;
    int slice, lb, nb;
    if (b < B0)           { slice = 0; lb = b;           nb = B0; }
    else if (b < B0 + B1) { slice = 1; lb = b - B0;      nb = B1; }
    else                  { slice = 2; lb = b - B0 - B1; nb = B2; }
    const int c0 = slice * 128;
    const int nchunk = (slice == 2) ? 8 : 16;  // valid uint4 chunks per row

    const uint4* gP = (const uint4*)g_Ph;  // row stride DP/8 = 40 uint4
    for (int idx = threadIdx.x; idx < KS * NL * nchunk; idx += ENC_THREADS) {
        int r = idx / nchunk, c = idx % nchunk;
        Pv[r * 16 + c] = gP[r * (DP / 8) + slice * 16 + c];
    }
    __syncthreads();

    const int lane  = threadIdx.x & 31;
    const int wid   = threadIdx.x >> 5;
    const int wsl   = lb * WPB + wid;
    const int nwarp = nb * WPB;

    const __half NH = __ushort_as_half((unsigned short)0xFC00);  // -inf
    const half2 NEGI = __halves2half2(NH, NH);

    if (slice < 2) {
        // ---- 128-ch slice: 2 words per warp (16-lane halves) ----
        const int lo   = lane & 15;
        const int half = lane >> 4;
        const int ch   = c0 + lo * 8;

        uint4 pk = g_wpk[2 * wsl + half];
        for (int p = wsl; p < NW / 2; p += nwarp) {
            const int pn = p + nwarp;
            uint4 nxt = make_uint4(0, 0, 0, 0);
            if (pn < NW / 2) nxt = g_wpk[2 * pn + half];

            unsigned lw[4] = {pk.x, pk.y, pk.z, pk.w};
            const int gw = 2 * p + half;

            INNER_BODY(lo)

            float2 f0 = __half22float2(m0), f1 = __half22float2(m1);
            float2 f2 = __half22float2(m2), f3 = __half22float2(m3);
            float* op = out + (size_t)gw * D + ch;
            float4 r;
            r.x = fmaxf(f0.x, 0.f); r.y = fmaxf(f0.y, 0.f);
            r.z = fmaxf(f1.x, 0.f); r.w = fmaxf(f1.y, 0.f);
            *(float4*)op = r;
            r.x = fmaxf(f2.x, 0.f); r.y = fmaxf(f2.y, 0.f);
            r.z = fmaxf(f3.x, 0.f); r.w = fmaxf(f3.y, 0.f);
            *(float4*)(op + 4) = r;

            pk = nxt;
        }
    } else {
        // ---- 64-ch slice (channels 256..299 real): 4 words per warp ----
        const int lo8 = lane & 7;
        const int g   = lane >> 3;
        const int ch  = c0 + lo8 * 8;  // 256..312

        uint4 pk = g_wpk[4 * wsl + g];
        for (int p = wsl; p < NW / 4; p += nwarp) {
            const int pn = p + nwarp;
            uint4 nxt = make_uint4(0, 0, 0, 0);
            if (pn < NW / 4) nxt = g_wpk[4 * pn + g];

            unsigned lw[4] = {pk.x, pk.y, pk.z, pk.w};
            const int gw = 4 * p + g;

            INNER_BODY(lo8)

            float2 f0 = __half22float2(m0), f1 = __half22float2(m1);
            float2 f2 = __half22float2(m2), f3 = __half22float2(m3);
            float* op = out + (size_t)gw * D + ch;
            if (ch < D) {
                float4 r;
                r.x = fmaxf(f0.x, 0.f); r.y = fmaxf(f0.y, 0.f);
                r.z = fmaxf(f1.x, 0.f); r.w = fmaxf(f1.y, 0.f);
                *(float4*)op = r;
            }
            if (ch + 4 < D) {
                float4 r;
                r.x = fmaxf(f2.x, 0.f); r.y = fmaxf(f2.y, 0.f);
                r.z = fmaxf(f3.x, 0.f); r.w = fmaxf(f3.y, 0.f);
                *(float4*)(op + 4) = r;
            }
            pk = nxt;
        }
    }
}

// ---------------------------------------------------------------------------
// Launch. Inputs: words(int32), emb(f32), conv_w(f32), conv_b(f32). Out f32.
// ---------------------------------------------------------------------------
extern "C" void kernel_launch(void* const* d_in, const int* in_sizes, int n_in,
                              void* d_out, int out_size) {
    const int*   words = (const int*)d_in[0];
    const float* emb   = (const float*)d_in[1];
    const float* w     = (const float*)d_in[2];
    const float* b     = (const float*)d_in[3];
    float*       out   = (float*)d_out;

    cudaFuncSetAttribute(prep_kernel,
                         cudaFuncAttributeMaxDynamicSharedMemorySize, PREP_SMEM);
    prep_kernel<<<PACK_BLOCKS + 107, 384, PREP_SMEM>>>(words, emb, w, b);

    cudaFuncSetAttribute(encode_kernel,
                         cudaFuncAttributeMaxDynamicSharedMemorySize, ENC_SMEM);
    encode_kernel<<<ENC_BLOCKS, ENC_THREADS, ENC_SMEM>>>(out);
}

// round 10
// speedup vs baseline: 1.0398x; 1.0398x over previous
#include <cuda_runtime.h>
#include <cuda_fp16.h>

// Problem constants
#define NW 16384   // words
#define WL 16      // word length
#define D  300     // hidden dim
#define DP 320     // padded channel count (zeros in [300,320))
#define NL 128     // letters
#define KS 3       // conv taps

// Encode config: slices 0/1 = 128 ch (2 words/warp), slice 2 = 64 ch
// (4 words/warp). 768 threads/CTA, 2 CTA/SM -> 48 warps/SM.
#define WPB 24
#define ENC_THREADS 768
#define B0 118
#define B1 118
#define B2 60
#define ENC_BLOCKS (B0 + B1 + B2)           // 296 = 2 CTA/SM * 148 SMs
#define ENC_SMEM (KS * NL * 128 * 2)        // 96 KB

// Device scratch
__device__ __half g_Ph[KS][NL][DP];  // per-letter conv partials (fp16, padded)
                                     // k=1 tap has conv bias folded in
__device__ float  g_embT[D * NL];    // emb transposed: [i][v]
__device__ uint4  g_wpk[NW];         // packed letters: 16 u8 per word

// ---------------------------------------------------------------------------
// Kernel A (prep): blocks 0-39 transpose emb [128][300] -> embT [300][128];
// blocks 40-103 pack each word's 16 letters into one uint4 of u8.
// (Measured 4.6 us in this exact form.)
// ---------------------------------------------------------------------------
__global__ __launch_bounds__(256) void prep_kernel(const float* __restrict__ emb,
                                                   const int* __restrict__ words) {
    if (blockIdx.x < 40) {
        __shared__ float t[32][33];
        const int bx = blockIdx.x % 10, by = blockIdx.x / 10;
        const int i0 = bx * 32, v0 = by * 32;
        const int x = threadIdx.x & 31, y = threadIdx.x >> 5;  // 32 x 8
#pragma unroll
        for (int dy = 0; dy < 32; dy += 8) {
            int v = v0 + y + dy, i = i0 + x;
            t[y + dy][x] = (i < D) ? emb[v * D + i] : 0.f;
        }
        __syncthreads();
#pragma unroll
        for (int dy = 0; dy < 32; dy += 8) {
            int i = i0 + y + dy, v = v0 + x;
            if (i < D) g_embT[i * NL + v] = t[x][y + dy];
        }
    } else {
        const int n = (blockIdx.x - 40) * 256 + threadIdx.x;
        unsigned r0 = 0, r1 = 0, r2 = 0, r3 = 0;
#pragma unroll
        for (int l = 0; l < 4; ++l)  r0 |= ((unsigned)words[l * NW + n] & 0xFF) << (l * 8);
#pragma unroll
        for (int l = 4; l < 8; ++l)  r1 |= ((unsigned)words[l * NW + n] & 0xFF) << ((l - 4) * 8);
#pragma unroll
        for (int l = 8; l < 12; ++l) r2 |= ((unsigned)words[l * NW + n] & 0xFF) << ((l - 8) * 8);
#pragma unroll
        for (int l = 12; l < 16; ++l) r3 |= ((unsigned)words[l * NW + n] & 0xFF) << ((l - 12) * 8);
        g_wpk[n] = make_uint4(r0, r1, r2, r3);
    }
}

// ---------------------------------------------------------------------------
// Kernel B: build P. 107 blocks x 384 threads = (3 output channels) x (128
// letters). embT reads fully coalesced (lane = v); w rows staged
// de-interleaved in smem. Bias folded into k=1 tap; zeros for o in [300,320).
// (Measured ~2.5 us in this form.)
// ---------------------------------------------------------------------------
__global__ __launch_bounds__(384) void compute_P_kernel(const float* __restrict__ w,
                                                        const float* __restrict__ bias) {
    __shared__ __align__(16) float ws[3][KS][304];  // 10.9 KB
    const int j = threadIdx.x >> 7;   // 0..2
    const int v = threadIdx.x & 127;
    const int o = blockIdx.x * 3 + j;
    const int ob = blockIdx.x * 3;

    for (int t = threadIdx.x; t < 3 * D * KS; t += 384) {
        int jj = t / (D * KS), r = t % (D * KS);
        int oo = ob + jj;
        ws[jj][r % 3][r / 3] = (oo < D) ? w[oo * D * KS + r] : 0.f;
    }
    __syncthreads();

    if (o >= DP) return;
    float a0 = 0.f, a1 = 0.f, a2 = 0.f;
    if (o < D) {
        const float* et = g_embT + v;  // stride NL, coalesced across lanes
#pragma unroll 5
        for (int i = 0; i < D; i += 4) {
            float4 w0 = *(const float4*)&ws[j][0][i];
            float4 w1 = *(const float4*)&ws[j][1][i];
            float4 w2 = *(const float4*)&ws[j][2][i];
            float e0 = et[(i + 0) * NL];
            float e1 = et[(i + 1) * NL];
            float e2 = et[(i + 2) * NL];
            float e3 = et[(i + 3) * NL];
            a0 = fmaf(e0, w0.x, a0); a1 = fmaf(e0, w1.x, a1); a2 = fmaf(e0, w2.x, a2);
            a0 = fmaf(e1, w0.y, a0); a1 = fmaf(e1, w1.y, a1); a2 = fmaf(e1, w2.y, a2);
            a0 = fmaf(e2, w0.z, a0); a1 = fmaf(e2, w1.z, a1); a2 = fmaf(e2, w2.z, a2);
            a0 = fmaf(e3, w0.w, a0); a1 = fmaf(e3, w1.w, a1); a2 = fmaf(e3, w2.w, a2);
        }
        a1 += bias[o];  // fold bias into the k=1 tap (exactly one per position)
    }
    g_Ph[0][v][o] = __float2half(a0);
    g_Ph[1][v][o] = __float2half(a1);
    g_Ph[2][v][o] = __float2half(a2);
}

// ---------------------------------------------------------------------------
// Kernel C: encode (identical to the 26.4 us round-9 kernel). 296 blocks
// (118/118/60), 768 thr, 2 CTA/SM, 48 warps/SM. Slices 0/1 (128 ch): 2
// words/warp. Slice 2 (64 ch): 4 words/warp. Letters via one broadcast
// LDG.128, prefetched. Per position: 3 conflict-free LDS.128 + half2 adds +
// half2 running max. Bias already in the table; epilogue = relu + store.
// ---------------------------------------------------------------------------
#define GETL(l) ((lw[(l) >> 2] >> (((l) & 3) * 8)) & 0xFF)

#define INNER_BODY(loidx)                                                        \
    half2 m0 = NEGI, m1 = NEGI, m2 = NEGI, m3 = NEGI;                            \
    _Pragma("unroll")                                                            \
    for (int l = 0; l < WL; ++l) {                                               \
        uint4 a = Pv[(NL + GETL(l)) * 16 + (loidx)];                             \
        half2 h0 = *(half2*)&a.x, h1 = *(half2*)&a.y;                            \
        half2 h2 = *(half2*)&a.z, h3 = *(half2*)&a.w;                            \
        if (l > 0) {                                                             \
            uint4 q = Pv[GETL(l - 1) * 16 + (loidx)];                            \
            h0 = __hadd2(h0, *(half2*)&q.x); h1 = __hadd2(h1, *(half2*)&q.y);    \
            h2 = __hadd2(h2, *(half2*)&q.z); h3 = __hadd2(h3, *(half2*)&q.w);    \
        }                                                                        \
        if (l < WL - 1) {                                                        \
            uint4 q = Pv[(2 * NL + GETL(l + 1)) * 16 + (loidx)];                 \
            h0 = __hadd2(h0, *(half2*)&q.x); h1 = __hadd2(h1, *(half2*)&q.y);    \
            h2 = __hadd2(h2, *(half2*)&q.z); h3 = __hadd2(h3, *(half2*)&q.w);    \
        }                                                                        \
        m0 = __hmax2(m0, h0); m1 = __hmax2(m1, h1);                              \
        m2 = __hmax2(m2, h2); m3 = __hmax2(m3, h3);                              \
    }

__global__ __launch_bounds__(ENC_THREADS, 2) void encode_kernel(float* __restrict__ out) {
    extern __shared__ uint4 Pv[];  // [KS*NL rows][16 uint4]

    int b = blockIdx.x;
    int slice, lb, nb;
    if (b < B0)           { slice = 0; lb = b;           nb = B0; }
    else if (b < B0 + B1) { slice = 1; lb = b - B0;      nb = B1; }
    else                  { slice = 2; lb = b - B0 - B1; nb = B2; }
    const int c0 = slice * 128;
    const int nchunk = (slice == 2) ? 8 : 16;  // valid uint4 chunks per row

    const uint4* gP = (const uint4*)g_Ph;  // row stride DP/8 = 40 uint4
    for (int idx = threadIdx.x; idx < KS * NL * nchunk; idx += ENC_THREADS) {
        int r = idx / nchunk, c = idx % nchunk;
        Pv[r * 16 + c] = gP[r * (DP / 8) + slice * 16 + c];
    }
    __syncthreads();

    const int lane  = threadIdx.x & 31;
    const int wid   = threadIdx.x >> 5;
    const int wsl   = lb * WPB + wid;
    const int nwarp = nb * WPB;

    const __half NH = __ushort_as_half((unsigned short)0xFC00);  // -inf
    const half2 NEGI = __halves2half2(NH, NH);

    if (slice < 2) {
        // ---- 128-ch slice: 2 words per warp (16-lane halves) ----
        const int lo   = lane & 15;
        const int half = lane >> 4;
        const int ch   = c0 + lo * 8;

        uint4 pk = g_wpk[2 * wsl + half];
        for (int p = wsl; p < NW / 2; p += nwarp) {
            const int pn = p + nwarp;
            uint4 nxt = make_uint4(0, 0, 0, 0);
            if (pn < NW / 2) nxt = g_wpk[2 * pn + half];

            unsigned lw[4] = {pk.x, pk.y, pk.z, pk.w};
            const int gw = 2 * p + half;

            INNER_BODY(lo)

            float2 f0 = __half22float2(m0), f1 = __half22float2(m1);
            float2 f2 = __half22float2(m2), f3 = __half22float2(m3);
            float* op = out + (size_t)gw * D + ch;
            float4 r;
            r.x = fmaxf(f0.x, 0.f); r.y = fmaxf(f0.y, 0.f);
            r.z = fmaxf(f1.x, 0.f); r.w = fmaxf(f1.y, 0.f);
            *(float4*)op = r;
            r.x = fmaxf(f2.x, 0.f); r.y = fmaxf(f2.y, 0.f);
            r.z = fmaxf(f3.x, 0.f); r.w = fmaxf(f3.y, 0.f);
            *(float4*)(op + 4) = r;

            pk = nxt;
        }
    } else {
        // ---- 64-ch slice (channels 256..299 real): 4 words per warp ----
        const int lo8 = lane & 7;
        const int g   = lane >> 3;
        const int ch  = c0 + lo8 * 8;  // 256..312

        uint4 pk = g_wpk[4 * wsl + g];
        for (int p = wsl; p < NW / 4; p += nwarp) {
            const int pn = p + nwarp;
            uint4 nxt = make_uint4(0, 0, 0, 0);
            if (pn < NW / 4) nxt = g_wpk[4 * pn + g];

            unsigned lw[4] = {pk.x, pk.y, pk.z, pk.w};
            const int gw = 4 * p + g;

            INNER_BODY(lo8)

            float2 f0 = __half22float2(m0), f1 = __half22float2(m1);
            float2 f2 = __half22float2(m2), f3 = __half22float2(m3);
            float* op = out + (size_t)gw * D + ch;
            if (ch < D) {
                float4 r;
                r.x = fmaxf(f0.x, 0.f); r.y = fmaxf(f0.y, 0.f);
                r.z = fmaxf(f1.x, 0.f); r.w = fmaxf(f1.y, 0.f);
                *(float4*)op = r;
            }
            if (ch + 4 < D) {
                float4 r;
                r.x = fmaxf(f2.x, 0.f); r.y = fmaxf(f2.y, 0.f);
                r.z = fmaxf(f3.x, 0.f); r.w = fmaxf(f3.y, 0.f);
                *(float4*)(op + 4) = r;
            }
            pk = nxt;
        }
    }
}

// ---------------------------------------------------------------------------
// Launch. Inputs: words(int32), emb(f32), conv_w(f32), conv_b(f32). Out f32.
// ---------------------------------------------------------------------------
extern "C" void kernel_launch(void* const* d_in, const int* in_sizes, int n_in,
                              void* d_out, int out_size) {
    const int*   words = (const int*)d_in[0];
    const float* emb   = (const float*)d_in[1];
    const float* w     = (const float*)d_in[2];
    const float* b     = (const float*)d_in[3];
    float*       out   = (float*)d_out;

    prep_kernel<<<104, 256>>>(emb, words);
    compute_P_kernel<<<107, 384>>>(w, b);

    cudaFuncSetAttribute(encode_kernel,
                         cudaFuncAttributeMaxDynamicSharedMemorySize, ENC_SMEM);
    encode_kernel<<<ENC_BLOCKS, ENC_THREADS, ENC_SMEM>>>(out);
}

// round 11
// speedup vs baseline: 1.1048x; 1.0626x over previous
#include <cuda_runtime.h>
#include <cuda_fp16.h>

// Problem constants
#define NW 16384   // words
#define WL 16      // word length
#define D  300     // hidden dim
#define DP 320     // padded channel count (zeros in [300,320))
#define NL 128     // letters
#define KS 3       // conv taps

// Encode config: slices 0/1 = 128 ch (2 words/warp), slice 2 = 64 ch
// (4 words/warp). 768 threads/CTA, 2 CTA/SM -> 48 warps/SM.
#define WPB 24
#define ENC_THREADS 768
#define B0 118
#define B1 118
#define B2 60
#define ENC_BLOCKS (B0 + B1 + B2)           // 296 = 2 CTA/SM * 148 SMs
#define ENC_SMEM (KS * NL * 128 * 2)        // 96 KB

// Fused prep: blocks [0,32) pack words (32*512 = 16384), blocks [32,112)
// build P (80 blocks x 4 channels = 320). 112 blocks = ONE wave @ 1 CTA/SM.
#define PACKB 32
#define PREP_BLOCKS 112
#define PREP_THREADS 512
#define ES_STRIDE 308   // floats; 308*4/16 = 77 quads, 77 mod 8 = 5 -> conflict-free LDS.128
#define PREP_SMEM ((NL * ES_STRIDE + 4 * KS * 304) * 4)  // 157696 + 14592 = 172288 B

// Device scratch
__device__ __half g_Ph[KS][NL][DP];  // per-letter conv partials (fp16, padded)
                                     // k=1 tap has conv bias folded in
__device__ uint4  g_wpk[NW];         // packed letters: 16 u8 per word

// packed-f32x2 FMA (FFMA2) — only reachable via PTX
__device__ __forceinline__ void fma2(unsigned long long& d,
                                     unsigned long long a, unsigned long long b) {
    asm("fma.rn.f32x2 %0, %1, %2, %0;" : "+l"(d) : "l"(a), "l"(b));
}
__device__ __forceinline__ float2 unpack2(unsigned long long x) {
    float2 f;
    asm("mov.b64 {%0, %1}, %2;" : "=f"(f.x), "=f"(f.y) : "l"(x));
    return f;
}

// ---------------------------------------------------------------------------
// Kernel 1 (fused prep, ONE wave):
//  blocks [0,32):  pack each word's 16 letters into one uint4 of u8.
//  blocks [32,112): P[k][v][o] = sum_i emb[v,i] * w[o,i,k] (+bias into k=1).
//    Whole emb staged in smem (coalesced), conflict-free row reads, FFMA2.
// ---------------------------------------------------------------------------
__global__ __launch_bounds__(PREP_THREADS) void prep_kernel(const int* __restrict__ words,
                                                            const float* __restrict__ emb,
                                                            const float* __restrict__ w,
                                                            const float* __restrict__ bias) {
    if (blockIdx.x < PACKB) {
        const int n = blockIdx.x * PREP_THREADS + threadIdx.x;
        unsigned r0 = 0, r1 = 0, r2 = 0, r3 = 0;
#pragma unroll
        for (int l = 0; l < 4; ++l)  r0 |= ((unsigned)words[l * NW + n] & 0xFF) << (l * 8);
#pragma unroll
        for (int l = 4; l < 8; ++l)  r1 |= ((unsigned)words[l * NW + n] & 0xFF) << ((l - 4) * 8);
#pragma unroll
        for (int l = 8; l < 12; ++l) r2 |= ((unsigned)words[l * NW + n] & 0xFF) << ((l - 8) * 8);
#pragma unroll
        for (int l = 12; l < 16; ++l) r3 |= ((unsigned)words[l * NW + n] & 0xFF) << ((l - 12) * 8);
        g_wpk[n] = make_uint4(r0, r1, r2, r3);
        return;
    }

    // ---- P branch: 4 output channels per block ----
    extern __shared__ float sm[];
    float* es = sm;                       // [128][ES_STRIDE]
    float* ws = sm + NL * ES_STRIDE;      // [4][KS][304]

    const int ob = (blockIdx.x - PACKB) * 4;
    const int j  = threadIdx.x >> 7;      // 0..3 (channel within block)
    const int v  = threadIdx.x & 127;     // letter
    const int o  = ob + j;

    // Stage emb [128][300] -> es (coalesced float4 reads & writes)
    const float4* e4 = (const float4*)emb;
    for (int idx = threadIdx.x; idx < NL * (D / 4); idx += PREP_THREADS) {
        int vv = idx / (D / 4), c = idx % (D / 4);
        *(float4*)&es[vv * ES_STRIDE + c * 4] = e4[idx];
    }
    // Stage w rows de-interleaved: ws[jj][k][i]
    for (int t = threadIdx.x; t < 4 * D * KS; t += PREP_THREADS) {
        int jj = t / (D * KS), r = t % (D * KS);
        int oo = ob + jj;
        ws[(jj * KS + r % 3) * 304 + r / 3] = (oo < D) ? w[oo * D * KS + r] : 0.f;
    }
    __syncthreads();

    typedef unsigned long long u64;
    u64 a0l = 0, a0h = 0, a1l = 0, a1h = 0, a2l = 0, a2h = 0;
    const float* ev  = es + v * ES_STRIDE;
    const float* w0p = ws + (j * KS + 0) * 304;
    const float* w1p = ws + (j * KS + 1) * 304;
    const float* w2p = ws + (j * KS + 2) * 304;
#pragma unroll 5
    for (int i = 0; i < D; i += 4) {
        ulonglong2 e2 = *(const ulonglong2*)(ev + i);   // (e_i,e_i+1),(e_i+2,e_i+3)
        ulonglong2 w0 = *(const ulonglong2*)(w0p + i);
        ulonglong2 w1 = *(const ulonglong2*)(w1p + i);
        ulonglong2 w2 = *(const ulonglong2*)(w2p + i);
        fma2(a0l, e2.x, w0.x); fma2(a0h, e2.y, w0.y);
        fma2(a1l, e2.x, w1.x); fma2(a1h, e2.y, w1.y);
        fma2(a2l, e2.x, w2.x); fma2(a2h, e2.y, w2.y);
    }
    float2 p0 = unpack2(a0l), q0 = unpack2(a0h);
    float2 p1 = unpack2(a1l), q1 = unpack2(a1h);
    float2 p2 = unpack2(a2l), q2 = unpack2(a2h);
    float a0 = (p0.x + p0.y) + (q0.x + q0.y);
    float a1 = (p1.x + p1.y) + (q1.x + q1.y);
    float a2 = (p2.x + p2.y) + (q2.x + q2.y);

    bool real = (o < D);
    float bv = real ? bias[o] : 0.f;
    g_Ph[0][v][o] = __float2half(real ? a0 : 0.f);
    g_Ph[1][v][o] = __float2half(real ? (a1 + bv) : 0.f);  // bias folded into k=1
    g_Ph[2][v][o] = __float2half(real ? a2 : 0.f);
}

// ---------------------------------------------------------------------------
// Kernel 2: encode (identical to the measured 26.4 us kernel). 296 blocks
// (118/118/60), 768 thr, 2 CTA/SM, 48 warps/SM. Slices 0/1 (128 ch): 2
// words/warp. Slice 2 (64 ch): 4 words/warp. Letters via one broadcast
// LDG.128, prefetched. Per position: 3 conflict-free LDS.128 + half2 adds +
// half2 running max. Bias already in the table; epilogue = relu + store.
// ---------------------------------------------------------------------------
#define GETL(l) ((lw[(l) >> 2] >> (((l) & 3) * 8)) & 0xFF)

#define INNER_BODY(loidx)                                                        \
    half2 m0 = NEGI, m1 = NEGI, m2 = NEGI, m3 = NEGI;                            \
    _Pragma("unroll")                                                            \
    for (int l = 0; l < WL; ++l) {                                               \
        uint4 a = Pv[(NL + GETL(l)) * 16 + (loidx)];                             \
        half2 h0 = *(half2*)&a.x, h1 = *(half2*)&a.y;                            \
        half2 h2 = *(half2*)&a.z, h3 = *(half2*)&a.w;                            \
        if (l > 0) {                                                             \
            uint4 q = Pv[GETL(l - 1) * 16 + (loidx)];                            \
            h0 = __hadd2(h0, *(half2*)&q.x); h1 = __hadd2(h1, *(half2*)&q.y);    \
            h2 = __hadd2(h2, *(half2*)&q.z); h3 = __hadd2(h3, *(half2*)&q.w);    \
        }                                                                        \
        if (l < WL - 1) {                                                        \
            uint4 q = Pv[(2 * NL + GETL(l + 1)) * 16 + (loidx)];                 \
            h0 = __hadd2(h0, *(half2*)&q.x); h1 = __hadd2(h1, *(half2*)&q.y);    \
            h2 = __hadd2(h2, *(half2*)&q.z); h3 = __hadd2(h3, *(half2*)&q.w);    \
        }                                                                        \
        m0 = __hmax2(m0, h0); m1 = __hmax2(m1, h1);                              \
        m2 = __hmax2(m2, h2); m3 = __hmax2(m3, h3);                              \
    }

__global__ __launch_bounds__(ENC_THREADS, 2) void encode_kernel(float* __restrict__ out) {
    extern __shared__ uint4 Pv[];  // [KS*NL rows][16 uint4]

    int b = blockIdx.x;
    int slice, lb, nb;
    if (b < B0)           { slice = 0; lb = b;           nb = B0; }
    else if (b < B0 + B1) { slice = 1; lb = b - B0;      nb = B1; }
    else                  { slice = 2; lb = b - B0 - B1; nb = B2; }
    const int c0 = slice * 128;
    const int nchunk = (slice == 2) ? 8 : 16;  // valid uint4 chunks per row

    const uint4* gP = (const uint4*)g_Ph;  // row stride DP/8 = 40 uint4
    for (int idx = threadIdx.x; idx < KS * NL * nchunk; idx += ENC_THREADS) {
        int r = idx / nchunk, c = idx % nchunk;
        Pv[r * 16 + c] = gP[r * (DP / 8) + slice * 16 + c];
    }
    __syncthreads();

    const int lane  = threadIdx.x & 31;
    const int wid   = threadIdx.x >> 5;
    const int wsl   = lb * WPB + wid;
    const int nwarp = nb * WPB;

    const __half NH = __ushort_as_half((unsigned short)0xFC00);  // -inf
    const half2 NEGI = __halves2half2(NH, NH);

    if (slice < 2) {
        // ---- 128-ch slice: 2 words per warp (16-lane halves) ----
        const int lo   = lane & 15;
        const int half = lane >> 4;
        const int ch   = c0 + lo * 8;

        uint4 pk = g_wpk[2 * wsl + half];
        for (int p = wsl; p < NW / 2; p += nwarp) {
            const int pn = p + nwarp;
            uint4 nxt = make_uint4(0, 0, 0, 0);
            if (pn < NW / 2) nxt = g_wpk[2 * pn + half];

            unsigned lw[4] = {pk.x, pk.y, pk.z, pk.w};
            const int gw = 2 * p + half;

            INNER_BODY(lo)

            float2 f0 = __half22float2(m0), f1 = __half22float2(m1);
            float2 f2 = __half22float2(m2), f3 = __half22float2(m3);
            float* op = out + (size_t)gw * D + ch;
            float4 r;
            r.x = fmaxf(f0.x, 0.f); r.y = fmaxf(f0.y, 0.f);
            r.z = fmaxf(f1.x, 0.f); r.w = fmaxf(f1.y, 0.f);
            *(float4*)op = r;
            r.x = fmaxf(f2.x, 0.f); r.y = fmaxf(f2.y, 0.f);
            r.z = fmaxf(f3.x, 0.f); r.w = fmaxf(f3.y, 0.f);
            *(float4*)(op + 4) = r;

            pk = nxt;
        }
    } else {
        // ---- 64-ch slice (channels 256..299 real): 4 words per warp ----
        const int lo8 = lane & 7;
        const int g   = lane >> 3;
        const int ch  = c0 + lo8 * 8;  // 256..312

        uint4 pk = g_wpk[4 * wsl + g];
        for (int p = wsl; p < NW / 4; p += nwarp) {
            const int pn = p + nwarp;
            uint4 nxt = make_uint4(0, 0, 0, 0);
            if (pn < NW / 4) nxt = g_wpk[4 * pn + g];

            unsigned lw[4] = {pk.x, pk.y, pk.z, pk.w};
            const int gw = 4 * p + g;

            INNER_BODY(lo8)

            float2 f0 = __half22float2(m0), f1 = __half22float2(m1);
            float2 f2 = __half22float2(m2), f3 = __half22float2(m3);
            float* op = out + (size_t)gw * D + ch;
            if (ch < D) {
                float4 r;
                r.x = fmaxf(f0.x, 0.f); r.y = fmaxf(f0.y, 0.f);
                r.z = fmaxf(f1.x, 0.f); r.w = fmaxf(f1.y, 0.f);
                *(float4*)op = r;
            }
            if (ch + 4 < D) {
                float4 r;
                r.x = fmaxf(f2.x, 0.f); r.y = fmaxf(f2.y, 0.f);
                r.z = fmaxf(f3.x, 0.f); r.w = fmaxf(f3.y, 0.f);
                *(float4*)(op + 4) = r;
            }
            pk = nxt;
        }
    }
}

// ---------------------------------------------------------------------------
// Launch. Inputs: words(int32), emb(f32), conv_w(f32), conv_b(f32). Out f32.
// ---------------------------------------------------------------------------
extern "C" void kernel_launch(void* const* d_in, const int* in_sizes, int n_in,
                              void* d_out, int out_size) {
    const int*   words = (const int*)d_in[0];
    const float* emb   = (const float*)d_in[1];
    const float* w     = (const float*)d_in[2];
    const float* b     = (const float*)d_in[3];
    float*       out   = (float*)d_out;

    cudaFuncSetAttribute(prep_kernel,
                         cudaFuncAttributeMaxDynamicSharedMemorySize, PREP_SMEM);
    prep_kernel<<<PREP_BLOCKS, PREP_THREADS, PREP_SMEM>>>(words, emb, w, b);

    cudaFuncSetAttribute(encode_kernel,
                         cudaFuncAttributeMaxDynamicSharedMemorySize, ENC_SMEM);
    encode_kernel<<<ENC_BLOCKS, ENC_THREADS, ENC_SMEM>>>(out);
}